// round 12
// baseline (speedup 1.0000x reference)
#include <cuda_runtime.h>
#include <cuda_fp16.h>
#include <stdint.h>

// Hybrid_Conv2d via warp-level mma.sync fp16 (m16n8k16) implicit GEMM.
// out[b] = conv2d(x[b], W0 + cov[b]*W1), 3x3 pad 1, B=32, C=64, 128x128.
//
// R11: 4-way cp.async pipeline (quarter-outer compute), SMEM-repacked
//      coalesced epilogue, uint4-vectorized prologue.
//  - CTA = (batch b, 4 image rows), 8 warps: warp = 64 px x 64 cout (m64n64).
//  - sA: [780 pos][32 kw + pad]; sB: [9 tap][64 co][32 kw + pad]; row stride
//    144B (mod 128 == 16) -> ldmatrix conflict-free.
//  - Epilogue: acc -> SMEM fp32 [64 co][524] (banks 24*ti+g, conflict-free)
//    -> float4 coalesced stores.

#define HW_   128
#define C_    64
#define B_    32
#define NT    256

#define SA_POS    780                 // 6 halo rows x 130 cols
#define ROWB      144                 // 128B data + 16B pad
#define SA_BYTES  (SA_POS * ROWB)     // 112320
#define SB_ROWS   (9 * 64)            // tap x co
#define SB_BYTES  (SB_ROWS * ROWB)    // 82944
#define SMEM_BYTES (SA_BYTES + SB_BYTES)   // 195264

#define SO_STRIDE 524                 // fp32 out-repack stride (mod 32 == 12)

__device__ __half   d_xh[(size_t)B_ * HW_ * HW_ * C_];   // [b][y][x][ci]
__device__ uint32_t d_Wcp[B_ * 9 * C_ * 32];  // [b][tap][co][kw], fp16x2(ci pair)

static __device__ __forceinline__ uint32_t smem_u32(const void* p) {
    uint32_t a;
    asm("{ .reg .u64 t; cvta.to.shared.u64 t, %1; cvt.u32.u64 %0, t; }" : "=r"(a) : "l"(p));
    return a;
}
static __device__ __forceinline__ void cp16(uint32_t dst, const void* src, int sz) {
    asm volatile("cp.async.cg.shared.global [%0], [%1], 16, %2;"
                 :: "r"(dst), "l"(src), "r"(sz) : "memory");
}
template <int N> static __device__ __forceinline__ void cp_wait() {
    asm volatile("cp.async.wait_group %0;" :: "n"(N) : "memory");
}
static __device__ __forceinline__ uint32_t packh2(float lo, float hi) {
    __half2 h = __floats2half2_rn(lo, hi);
    return *reinterpret_cast<uint32_t*>(&h);
}
#define LDSM_X4(r0, r1, r2, r3, addr)                                        \
    asm volatile("ldmatrix.sync.aligned.m8n8.x4.shared.b16 {%0,%1,%2,%3}, [%4];" \
        : "=r"(r0), "=r"(r1), "=r"(r2), "=r"(r3) : "r"(addr))

// ---- fused prologue: transpose x to channels-last fp16 + build weights ----
__global__ void prologue_kernel(const float* __restrict__ x,
                                const float* __restrict__ W0,
                                const float* __restrict__ W1,
                                const float* __restrict__ cov) {
    const int b = blockIdx.y;
    if (blockIdx.x < HW_) {
        __shared__ float sT[C_][HW_ + 1];
        const int y = blockIdx.x;
        const float4* src = (const float4*)(x + ((size_t)(b * C_) * HW_ + y) * HW_);
        for (int e = threadIdx.x; e < C_ * (HW_ / 4); e += NT) {
            const int ci = e >> 5, xq = e & 31;
            float4 v = src[(size_t)ci * (HW_ * HW_ / 4) + xq];
            sT[ci][xq * 4]     = v.x;
            sT[ci][xq * 4 + 1] = v.y;
            sT[ci][xq * 4 + 2] = v.z;
            sT[ci][xq * 4 + 3] = v.w;
        }
        __syncthreads();
        uint4* dst = (uint4*)(d_xh + ((size_t)(b * HW_) + y) * HW_ * C_);
        for (int e = threadIdx.x; e < HW_ * 8; e += NT) {
            const int xx = e >> 3, kq = e & 7;   // kq = group of 4 kw
            uint4 w;
            w.x = packh2(sT[8 * kq    ][xx], sT[8 * kq + 1][xx]);
            w.y = packh2(sT[8 * kq + 2][xx], sT[8 * kq + 3][xx]);
            w.z = packh2(sT[8 * kq + 4][xx], sT[8 * kq + 5][xx]);
            w.w = packh2(sT[8 * kq + 6][xx], sT[8 * kq + 7][xx]);
            dst[xx * 8 + kq] = w;
        }
    } else {
        const int tap = blockIdx.x - HW_;     // 0..8
        const float cv = cov[b];
        for (int i = threadIdx.x; i < C_ * 32; i += NT) {
            const int co = i >> 5, kw = i & 31;
            const int g0 = (co * C_ + 2 * kw) * 9 + tap;
            d_Wcp[((b * 9 + tap) * C_ + co) * 32 + kw] =
                packh2(W0[g0] + cv * W1[g0], W0[g0 + 9] + cv * W1[g0 + 9]);
        }
    }
}

extern __shared__ uint32_t smem_dyn[];

__global__ __launch_bounds__(NT, 1)
void hybrid_conv_mma_kernel(float* __restrict__ out) {
    const int tid = threadIdx.x;
    const int wa  = tid >> 5;
    const int lid = tid & 31;
    const int g   = lid >> 2;
    const int ti  = lid & 3;
    const int y0  = blockIdx.x * 4;
    const int b   = blockIdx.y;

    const uint32_t sa_base = smem_u32(smem_dyn);
    const uint32_t sb_base = sa_base + SA_BYTES;

    // ---- staging: G0 = B + A kw-quarter 0; G1..G3 = A kw-quarters 1..3 ----
    // per-thread A geometry (pos pairs): q in {tid, tid+256, ...} over 780*2
    #pragma unroll
    for (int grp = 0; grp < 4; grp++) {
        if (grp == 0) {
            for (int q = tid; q < SB_ROWS * 8; q += NT) {
                const int row = q >> 3, ch = q & 7;
                cp16(sb_base + row * ROWB + ch * 16,
                     d_Wcp + ((size_t)(b * SB_ROWS) + row) * 32 + ch * 4, 16);
            }
        }
        for (int q = tid; q < SA_POS * 2; q += NT) {
            const int pos = q >> 1, ch = (q & 1) + grp * 2;
            const int r = pos / 130, c = pos - r * 130;
            const int gy = y0 - 1 + r, gx = c - 1;
            const bool ok = ((unsigned)gy < (unsigned)HW_) & ((unsigned)gx < (unsigned)HW_);
            const __half* src = d_xh + (((size_t)(b * HW_ + (ok ? gy : 0)) * HW_
                                   + (ok ? gx : 0)) * C_ + ch * 8);
            cp16(sa_base + pos * ROWB + ch * 16, src, ok ? 16 : 0);
        }
        asm volatile("cp.async.commit_group;" ::: "memory");
    }

    float acc[4][8][4];
    #pragma unroll
    for (int mt = 0; mt < 4; mt++)
        #pragma unroll
        for (int nt = 0; nt < 8; nt++)
            #pragma unroll
            for (int r = 0; r < 4; r++) acc[mt][nt][r] = 0.0f;

    // per-lane ldmatrix address components (same mapping as R10)
    const int pwarp  = (wa >> 1) * 130 + (wa & 1) * 64;
    const uint32_t laneA  = (uint32_t)((lid & 15) * ROWB + ((lid & 16) ? 16 : 0));
    const int      laneBc = (lid & 7) + ((lid >> 4) << 3);
    const uint32_t laneBk = (lid & 8) ? 16u : 0u;

    // ---- compute: 4 kw-quarters (pipelined) x 9 taps x 16 MMAs ----
    #pragma unroll
    for (int qk = 0; qk < 4; qk++) {
        if (qk == 0) cp_wait<3>();
        else if (qk == 1) cp_wait<2>();
        else if (qk == 2) cp_wait<1>();
        else cp_wait<0>();
        __syncthreads();
        const uint32_t kbyte = (uint32_t)(qk * 32);

        #pragma unroll 1
        for (int tap = 0; tap < 9; tap++) {
            const int ky = tap / 3;
            const int pb = pwarp + ky * 130 + (tap - ky * 3);
            const uint32_t sbt = sb_base + (uint32_t)(tap * 64 * ROWB);
            uint32_t a[4][4];
            #pragma unroll
            for (int mt = 0; mt < 4; mt++) {
                const uint32_t ad = sa_base
                    + (uint32_t)((pb + mt * 16) * ROWB) + kbyte + laneA;
                LDSM_X4(a[mt][0], a[mt][1], a[mt][2], a[mt][3], ad);
            }
            #pragma unroll
            for (int q = 0; q < 4; q++) {
                uint32_t b0, b1, b2, b3;
                const uint32_t bd = sbt
                    + (uint32_t)((16 * q + laneBc) * ROWB) + kbyte + laneBk;
                LDSM_X4(b0, b1, b2, b3, bd);
                #pragma unroll
                for (int mt = 0; mt < 4; mt++) {
                    asm volatile(
                        "mma.sync.aligned.m16n8k16.row.col.f32.f16.f16.f32 "
                        "{%0,%1,%2,%3}, {%4,%5,%6,%7}, {%8,%9}, {%0,%1,%2,%3};"
                        : "+f"(acc[mt][2 * q][0]), "+f"(acc[mt][2 * q][1]),
                          "+f"(acc[mt][2 * q][2]), "+f"(acc[mt][2 * q][3])
                        : "r"(a[mt][0]), "r"(a[mt][1]), "r"(a[mt][2]),
                          "r"(a[mt][3]), "r"(b0), "r"(b1));
                }
                #pragma unroll
                for (int mt = 0; mt < 4; mt++) {
                    asm volatile(
                        "mma.sync.aligned.m16n8k16.row.col.f32.f16.f16.f32 "
                        "{%0,%1,%2,%3}, {%4,%5,%6,%7}, {%8,%9}, {%0,%1,%2,%3};"
                        : "+f"(acc[mt][2 * q + 1][0]), "+f"(acc[mt][2 * q + 1][1]),
                          "+f"(acc[mt][2 * q + 1][2]), "+f"(acc[mt][2 * q + 1][3])
                        : "r"(a[mt][0]), "r"(a[mt][1]), "r"(a[mt][2]),
                          "r"(a[mt][3]), "r"(b2), "r"(b3));
                }
            }
        }
    }

    // ---- epilogue: repack through SMEM, then coalesced float4 stores ----
    __syncthreads();                           // all reads of slab done
    float* sOut = (float*)smem_dyn;            // [64 co][SO_STRIDE]
    {
        const int pbase = (wa >> 1) * 128 + (wa & 1) * 64;   // px in CTA
        #pragma unroll
        for (int mt = 0; mt < 4; mt++) {
            const int p = pbase + mt * 16 + g;
            #pragma unroll
            for (int nt = 0; nt < 8; nt++) {
                const int n = nt * 8 + 2 * ti;
                sOut[n * SO_STRIDE + p]           = acc[mt][nt][0];
                sOut[(n + 1) * SO_STRIDE + p]     = acc[mt][nt][1];
                sOut[n * SO_STRIDE + p + 8]       = acc[mt][nt][2];
                sOut[(n + 1) * SO_STRIDE + p + 8] = acc[mt][nt][3];
            }
        }
    }
    __syncthreads();
    {
        float4* ob = (float4*)(out + ((size_t)(b * C_) * HW_ + y0) * HW_);
        // 64 co x 512 px = 8192 float4; 32 per thread
        #pragma unroll
        for (int i = 0; i < 32; i++) {
            const int iq = i * NT + tid;
            const int co = iq >> 7;            // 128 float4 per co
            const int f  = iq & 127;           // p = 4*f
            const float4 v = *(const float4*)&sOut[co * SO_STRIDE + 4 * f];
            ob[(size_t)co * (HW_ * HW_ / 4) + f] = v;
        }
    }
}

extern "C" void kernel_launch(void* const* d_in, const int* in_sizes, int n_in,
                              void* d_out, int out_size) {
    (void)in_sizes; (void)n_in; (void)out_size;
    const float* x   = (const float*)d_in[0];
    const float* cov = (const float*)d_in[1];
    const float* W0  = (const float*)d_in[2];
    const float* W1  = (const float*)d_in[3];
    float* out = (float*)d_out;

    prologue_kernel<<<dim3(HW_ + 9, B_), NT>>>(x, W0, W1, cov);

    cudaFuncSetAttribute(hybrid_conv_mma_kernel,
                         cudaFuncAttributeMaxDynamicSharedMemorySize, SMEM_BYTES);
    hybrid_conv_mma_kernel<<<dim3(HW_ / 4, B_), NT, SMEM_BYTES>>>(out);
}

// round 13
// speedup vs baseline: 1.5985x; 1.5985x over previous
#include <cuda_runtime.h>
#include <cuda_fp16.h>
#include <stdint.h>

// Hybrid_Conv2d via warp-level mma.sync fp16 (m16n8k16) implicit GEMM.
// out[b] = conv2d(x[b], W0 + cov[b]*W1), 3x3 pad 1, B=32, C=64, 128x128.
//
// R12: R10 structure (compute loop, epilogue, 2-group first-stage) kept
//      verbatim; NEW: persistent CTAs (grid=152, tile stride 152). Each CTA
//      loops over ~7 (batch,row-tile) tiles; after the last ldmatrix of tile
//      t it prefetches tile t+1's A+B slab via one cp.async group, hiding
//      staging latency behind the epilogue + loop entry.
//  - CTA tile = (batch b, 4 image rows), 8 warps: warp = 64 px x 64 cout.
//  - sA: [780 pos][32 kw + pad]; sB: [9 tap][64 co][32 kw + pad]; row stride
//    144B (mod 128 == 16) -> ldmatrix conflict-free.

#define HW_   128
#define C_    64
#define B_    32
#define NT    256
#define NTILES 1024              // 32 batches x 32 row-tiles
#define GRID_P 152               // GB300 SM count

#define SA_POS    780            // 6 halo rows x 130 cols
#define ROWB      144            // 128B data + 16B pad
#define SA_BYTES  (SA_POS * ROWB)     // 112320
#define SB_ROWS   (9 * 64)            // tap x co
#define SB_BYTES  (SB_ROWS * ROWB)    // 82944
#define SMEM_BYTES (SA_BYTES + SB_BYTES)   // 195264

__device__ __half   d_xh[(size_t)B_ * HW_ * HW_ * C_];   // [b][y][x][ci]
__device__ uint32_t d_Wcp[B_ * 9 * C_ * 32];  // [b][tap][co][kw], fp16x2(ci pair)

static __device__ __forceinline__ uint32_t smem_u32(const void* p) {
    uint32_t a;
    asm("{ .reg .u64 t; cvta.to.shared.u64 t, %1; cvt.u32.u64 %0, t; }" : "=r"(a) : "l"(p));
    return a;
}
static __device__ __forceinline__ void cp16(uint32_t dst, const void* src, int sz) {
    asm volatile("cp.async.cg.shared.global [%0], [%1], 16, %2;"
                 :: "r"(dst), "l"(src), "r"(sz) : "memory");
}
template <int N> static __device__ __forceinline__ void cp_wait() {
    asm volatile("cp.async.wait_group %0;" :: "n"(N) : "memory");
}
static __device__ __forceinline__ uint32_t packh2(float lo, float hi) {
    __half2 h = __floats2half2_rn(lo, hi);
    return *reinterpret_cast<uint32_t*>(&h);
}
#define LDSM_X4(r0, r1, r2, r3, addr)                                        \
    asm volatile("ldmatrix.sync.aligned.m8n8.x4.shared.b16 {%0,%1,%2,%3}, [%4];" \
        : "=r"(r0), "=r"(r1), "=r"(r2), "=r"(r3) : "r"(addr))

// ---- fused prologue: transpose x to channels-last fp16 + build weights ----
// (identical to R10)
__global__ void prologue_kernel(const float* __restrict__ x,
                                const float* __restrict__ W0,
                                const float* __restrict__ W1,
                                const float* __restrict__ cov) {
    const int b = blockIdx.y;
    if (blockIdx.x < HW_) {
        __shared__ float sT[C_][HW_ + 1];
        const int y = blockIdx.x;
        const float4* src = (const float4*)(x + ((size_t)(b * C_) * HW_ + y) * HW_);
        for (int e = threadIdx.x; e < C_ * (HW_ / 4); e += NT) {
            const int ci = e >> 5, xq = e & 31;
            float4 v = src[(size_t)ci * (HW_ * HW_ / 4) + xq];
            sT[ci][xq * 4]     = v.x;
            sT[ci][xq * 4 + 1] = v.y;
            sT[ci][xq * 4 + 2] = v.z;
            sT[ci][xq * 4 + 3] = v.w;
        }
        __syncthreads();
        uint32_t* dst = (uint32_t*)(d_xh + ((size_t)(b * HW_) + y) * HW_ * C_);
        for (int e = threadIdx.x; e < HW_ * 32; e += NT) {
            const int xx = e >> 5, kw = e & 31;
            dst[xx * 32 + kw] = packh2(sT[2 * kw][xx], sT[2 * kw + 1][xx]);
        }
    } else {
        const int tap = blockIdx.x - HW_;     // 0..8
        const float cv = cov[b];
        for (int i = threadIdx.x; i < C_ * 32; i += NT) {
            const int co = i >> 5, kw = i & 31;
            const int g0 = (co * C_ + 2 * kw) * 9 + tap;
            d_Wcp[((b * 9 + tap) * C_ + co) * 32 + kw] =
                packh2(W0[g0] + cv * W1[g0], W0[g0 + 9] + cv * W1[g0 + 9]);
        }
    }
}

extern __shared__ uint32_t smem_dyn[];

__global__ __launch_bounds__(NT, 1)
void hybrid_conv_mma_kernel(float* __restrict__ out) {
    const int tid = threadIdx.x;
    const int wa  = tid >> 5;
    const int lid = tid & 31;
    const int g   = lid >> 2;
    const int ti  = lid & 3;

    const uint32_t sa_base = smem_u32(smem_dyn);
    const uint32_t sb_base = sa_base + SA_BYTES;

    // stage helpers (same cp16 pattern as R10)
    auto stageA4 = [&](int bn, int y0n, int chb) {
        for (int q = tid; q < SA_POS * 4; q += NT) {
            const int pos = q >> 2, ch = (q & 3) + chb;
            const int r = pos / 130, c = pos - r * 130;
            const int gy = y0n - 1 + r, gx = c - 1;
            const bool ok = ((unsigned)gy < (unsigned)HW_) & ((unsigned)gx < (unsigned)HW_);
            const __half* src = d_xh + (((size_t)(bn * HW_ + (ok ? gy : 0)) * HW_
                                   + (ok ? gx : 0)) * C_ + ch * 8);
            cp16(sa_base + pos * ROWB + ch * 16, src, ok ? 16 : 0);
        }
    };
    auto stageB = [&](int bn) {
        for (int q = tid; q < SB_ROWS * 8; q += NT) {
            const int row = q >> 3, ch = q & 7;
            cp16(sb_base + row * ROWB + ch * 16,
                 d_Wcp + ((size_t)(bn * SB_ROWS) + row) * 32 + ch * 4, 16);
        }
    };

    // per-lane ldmatrix address components (same mapping as R10)
    const int pwarp  = (wa >> 1) * 130 + (wa & 1) * 64;
    const uint32_t laneA  = (uint32_t)((lid & 15) * ROWB + ((lid & 16) ? 16 : 0));
    const int      laneBc = (lid & 7) + ((lid >> 4) << 3);
    const uint32_t laneBk = (lid & 8) ? 16u : 0u;

    // ---- first tile: 2-group staged exactly like R10 ----
    int t = blockIdx.x;
    {
        const int bn = t >> 5, y0n = (t & 31) * 4;
        stageB(bn);
        stageA4(bn, y0n, 0);
        asm volatile("cp.async.commit_group;" ::: "memory");
        stageA4(bn, y0n, 4);
        asm volatile("cp.async.commit_group;" ::: "memory");
    }

    bool first = true;
    while (t < NTILES) {
        const int b  = t >> 5;
        const int y0 = (t & 31) * 4;

        float acc[4][8][4];
        #pragma unroll
        for (int mt = 0; mt < 4; mt++)
            #pragma unroll
            for (int nt = 0; nt < 8; nt++)
                #pragma unroll
                for (int r = 0; r < 4; r++) acc[mt][nt][r] = 0.0f;

        // ---- compute: 2 halves x 9 taps x 2 ks x 16 MMAs (R10 verbatim) ----
        #pragma unroll
        for (int half = 0; half < 2; half++) {
            if (first) {
                if (half == 0) cp_wait<1>(); else cp_wait<0>();
                __syncthreads();
            } else if (half == 0) {
                cp_wait<0>();
                __syncthreads();
            }

            #pragma unroll 1
            for (int tap = 0; tap < 9; tap++) {
                const int ky = tap / 3;
                const int pb = pwarp + ky * 130 + (tap - ky * 3);
                const uint32_t sbt = sb_base + (uint32_t)(tap * 64 * ROWB);
                #pragma unroll
                for (int ks2 = 0; ks2 < 2; ks2++) {
                    const uint32_t kbyte = (uint32_t)((half * 2 + ks2) * 32);
                    uint32_t a[4][4];
                    #pragma unroll
                    for (int mt = 0; mt < 4; mt++) {
                        const uint32_t ad = sa_base
                            + (uint32_t)((pb + mt * 16) * ROWB) + kbyte + laneA;
                        LDSM_X4(a[mt][0], a[mt][1], a[mt][2], a[mt][3], ad);
                    }
                    #pragma unroll
                    for (int q = 0; q < 4; q++) {
                        uint32_t b0, b1, b2, b3;
                        const uint32_t bd = sbt
                            + (uint32_t)((16 * q + laneBc) * ROWB) + kbyte + laneBk;
                        LDSM_X4(b0, b1, b2, b3, bd);
                        #pragma unroll
                        for (int mt = 0; mt < 4; mt++) {
                            asm volatile(
                                "mma.sync.aligned.m16n8k16.row.col.f32.f16.f16.f32 "
                                "{%0,%1,%2,%3}, {%4,%5,%6,%7}, {%8,%9}, {%0,%1,%2,%3};"
                                : "+f"(acc[mt][2 * q][0]), "+f"(acc[mt][2 * q][1]),
                                  "+f"(acc[mt][2 * q][2]), "+f"(acc[mt][2 * q][3])
                                : "r"(a[mt][0]), "r"(a[mt][1]), "r"(a[mt][2]),
                                  "r"(a[mt][3]), "r"(b0), "r"(b1));
                        }
                        #pragma unroll
                        for (int mt = 0; mt < 4; mt++) {
                            asm volatile(
                                "mma.sync.aligned.m16n8k16.row.col.f32.f16.f16.f32 "
                                "{%0,%1,%2,%3}, {%4,%5,%6,%7}, {%8,%9}, {%0,%1,%2,%3};"
                                : "+f"(acc[mt][2 * q + 1][0]), "+f"(acc[mt][2 * q + 1][1]),
                                  "+f"(acc[mt][2 * q + 1][2]), "+f"(acc[mt][2 * q + 1][3])
                                : "r"(a[mt][0]), "r"(a[mt][1]), "r"(a[mt][2]),
                                  "r"(a[mt][3]), "r"(b2), "r"(b3));
                        }
                    }
                }
            }
        }

        // ---- prefetch next tile's slab (after all reads of this slab) ----
        __syncthreads();
        const int tn = t + GRID_P;
        if (tn < NTILES) {
            const int bn = tn >> 5, y0n = (tn & 31) * 4;
            stageB(bn);
            stageA4(bn, y0n, 0);
            stageA4(bn, y0n, 4);
            asm volatile("cp.async.commit_group;" ::: "memory");
        }

        // ---- epilogue: acc -> out[b][co][row][col] (R10 verbatim) ----
        {
            const int row   = y0 + (wa >> 1);
            const int cbase = (wa & 1) * 64;
            #pragma unroll
            for (int mt = 0; mt < 4; mt++) {
                const int col = cbase + mt * 16 + g;
                #pragma unroll
                for (int nt = 0; nt < 8; nt++) {
                    const int n = nt * 8 + 2 * ti;
                    float* op = out + (((size_t)(b * C_ + n) * HW_) + row) * HW_;
                    op[col]                 = acc[mt][nt][0];
                    op[HW_ * HW_ + col]     = acc[mt][nt][1];   // cout n+1
                    op[col + 8]             = acc[mt][nt][2];
                    op[HW_ * HW_ + col + 8] = acc[mt][nt][3];
                }
            }
        }

        t = tn;
        first = false;
    }
}

extern "C" void kernel_launch(void* const* d_in, const int* in_sizes, int n_in,
                              void* d_out, int out_size) {
    (void)in_sizes; (void)n_in; (void)out_size;
    const float* x   = (const float*)d_in[0];
    const float* cov = (const float*)d_in[1];
    const float* W0  = (const float*)d_in[2];
    const float* W1  = (const float*)d_in[3];
    float* out = (float*)d_out;

    prologue_kernel<<<dim3(HW_ + 9, B_), NT>>>(x, W0, W1, cov);

    cudaFuncSetAttribute(hybrid_conv_mma_kernel,
                         cudaFuncAttributeMaxDynamicSharedMemorySize, SMEM_BYTES);
    hybrid_conv_mma_kernel<<<dim3(GRID_P), NT, SMEM_BYTES>>>(out);
}

// round 14
// speedup vs baseline: 1.6024x; 1.0024x over previous
#include <cuda_runtime.h>
#include <cuda_fp16.h>
#include <stdint.h>

// Hybrid_Conv2d via warp-level mma.sync fp16 (m16n8k16) implicit GEMM.
// out[b] = conv2d(x[b], W0 + cov[b]*W1), 3x3 pad 1, B=32, C=64, 128x128.
//
// R13: R12 (persistent CTAs + slab prefetch) with ONE change: all 8 fragment
//      ldmatrix ops (4 A + 4 B) hoisted to the top of each (tap,ks) iteration,
//      so the 32 MMAs run as an uninterrupted burst with >=8-issue-slot
//      distance from every LDSM producer (covers LDSM latency with only
//      2 warps/SMSP).
//  - CTA tile = (batch b, 4 image rows), 8 warps: warp = 64 px x 64 cout.
//  - sA: [780 pos][32 kw + pad]; sB: [9 tap][64 co][32 kw + pad]; row stride
//    144B (mod 128 == 16) -> ldmatrix conflict-free.

#define HW_   128
#define C_    64
#define B_    32
#define NT    256
#define NTILES 1024              // 32 batches x 32 row-tiles
#define GRID_P 152               // GB300 SM count

#define SA_POS    780            // 6 halo rows x 130 cols
#define ROWB      144            // 128B data + 16B pad
#define SA_BYTES  (SA_POS * ROWB)     // 112320
#define SB_ROWS   (9 * 64)            // tap x co
#define SB_BYTES  (SB_ROWS * ROWB)    // 82944
#define SMEM_BYTES (SA_BYTES + SB_BYTES)   // 195264

__device__ __half   d_xh[(size_t)B_ * HW_ * HW_ * C_];   // [b][y][x][ci]
__device__ uint32_t d_Wcp[B_ * 9 * C_ * 32];  // [b][tap][co][kw], fp16x2(ci pair)

static __device__ __forceinline__ uint32_t smem_u32(const void* p) {
    uint32_t a;
    asm("{ .reg .u64 t; cvta.to.shared.u64 t, %1; cvt.u32.u64 %0, t; }" : "=r"(a) : "l"(p));
    return a;
}
static __device__ __forceinline__ void cp16(uint32_t dst, const void* src, int sz) {
    asm volatile("cp.async.cg.shared.global [%0], [%1], 16, %2;"
                 :: "r"(dst), "l"(src), "r"(sz) : "memory");
}
template <int N> static __device__ __forceinline__ void cp_wait() {
    asm volatile("cp.async.wait_group %0;" :: "n"(N) : "memory");
}
static __device__ __forceinline__ uint32_t packh2(float lo, float hi) {
    __half2 h = __floats2half2_rn(lo, hi);
    return *reinterpret_cast<uint32_t*>(&h);
}
#define LDSM_X4(r0, r1, r2, r3, addr)                                        \
    asm volatile("ldmatrix.sync.aligned.m8n8.x4.shared.b16 {%0,%1,%2,%3}, [%4];" \
        : "=r"(r0), "=r"(r1), "=r"(r2), "=r"(r3) : "r"(addr))

// ---- fused prologue: transpose x to channels-last fp16 + build weights ----
// (identical to R10/R12)
__global__ void prologue_kernel(const float* __restrict__ x,
                                const float* __restrict__ W0,
                                const float* __restrict__ W1,
                                const float* __restrict__ cov) {
    const int b = blockIdx.y;
    if (blockIdx.x < HW_) {
        __shared__ float sT[C_][HW_ + 1];
        const int y = blockIdx.x;
        const float4* src = (const float4*)(x + ((size_t)(b * C_) * HW_ + y) * HW_);
        for (int e = threadIdx.x; e < C_ * (HW_ / 4); e += NT) {
            const int ci = e >> 5, xq = e & 31;
            float4 v = src[(size_t)ci * (HW_ * HW_ / 4) + xq];
            sT[ci][xq * 4]     = v.x;
            sT[ci][xq * 4 + 1] = v.y;
            sT[ci][xq * 4 + 2] = v.z;
            sT[ci][xq * 4 + 3] = v.w;
        }
        __syncthreads();
        uint32_t* dst = (uint32_t*)(d_xh + ((size_t)(b * HW_) + y) * HW_ * C_);
        for (int e = threadIdx.x; e < HW_ * 32; e += NT) {
            const int xx = e >> 5, kw = e & 31;
            dst[xx * 32 + kw] = packh2(sT[2 * kw][xx], sT[2 * kw + 1][xx]);
        }
    } else {
        const int tap = blockIdx.x - HW_;     // 0..8
        const float cv = cov[b];
        for (int i = threadIdx.x; i < C_ * 32; i += NT) {
            const int co = i >> 5, kw = i & 31;
            const int g0 = (co * C_ + 2 * kw) * 9 + tap;
            d_Wcp[((b * 9 + tap) * C_ + co) * 32 + kw] =
                packh2(W0[g0] + cv * W1[g0], W0[g0 + 9] + cv * W1[g0 + 9]);
        }
    }
}

extern __shared__ uint32_t smem_dyn[];

__global__ __launch_bounds__(NT, 1)
void hybrid_conv_mma_kernel(float* __restrict__ out) {
    const int tid = threadIdx.x;
    const int wa  = tid >> 5;
    const int lid = tid & 31;
    const int g   = lid >> 2;
    const int ti  = lid & 3;

    const uint32_t sa_base = smem_u32(smem_dyn);
    const uint32_t sb_base = sa_base + SA_BYTES;

    auto stageA4 = [&](int bn, int y0n, int chb) {
        for (int q = tid; q < SA_POS * 4; q += NT) {
            const int pos = q >> 2, ch = (q & 3) + chb;
            const int r = pos / 130, c = pos - r * 130;
            const int gy = y0n - 1 + r, gx = c - 1;
            const bool ok = ((unsigned)gy < (unsigned)HW_) & ((unsigned)gx < (unsigned)HW_);
            const __half* src = d_xh + (((size_t)(bn * HW_ + (ok ? gy : 0)) * HW_
                                   + (ok ? gx : 0)) * C_ + ch * 8);
            cp16(sa_base + pos * ROWB + ch * 16, src, ok ? 16 : 0);
        }
    };
    auto stageB = [&](int bn) {
        for (int q = tid; q < SB_ROWS * 8; q += NT) {
            const int row = q >> 3, ch = q & 7;
            cp16(sb_base + row * ROWB + ch * 16,
                 d_Wcp + ((size_t)(bn * SB_ROWS) + row) * 32 + ch * 4, 16);
        }
    };

    // per-lane ldmatrix address components
    const int pwarp  = (wa >> 1) * 130 + (wa & 1) * 64;
    const uint32_t laneA  = (uint32_t)((lid & 15) * ROWB + ((lid & 16) ? 16 : 0));
    const int      laneBc = (lid & 7) + ((lid >> 4) << 3);
    const uint32_t laneBk = (lid & 8) ? 16u : 0u;

    // ---- first tile: 2-group staged ----
    int t = blockIdx.x;
    {
        const int bn = t >> 5, y0n = (t & 31) * 4;
        stageB(bn);
        stageA4(bn, y0n, 0);
        asm volatile("cp.async.commit_group;" ::: "memory");
        stageA4(bn, y0n, 4);
        asm volatile("cp.async.commit_group;" ::: "memory");
    }

    bool first = true;
    while (t < NTILES) {
        const int b  = t >> 5;
        const int y0 = (t & 31) * 4;

        float acc[4][8][4];
        #pragma unroll
        for (int mt = 0; mt < 4; mt++)
            #pragma unroll
            for (int nt = 0; nt < 8; nt++)
                #pragma unroll
                for (int r = 0; r < 4; r++) acc[mt][nt][r] = 0.0f;

        #pragma unroll
        for (int half = 0; half < 2; half++) {
            if (first) {
                if (half == 0) cp_wait<1>(); else cp_wait<0>();
                __syncthreads();
            } else if (half == 0) {
                cp_wait<0>();
                __syncthreads();
            }

            #pragma unroll 1
            for (int tap = 0; tap < 9; tap++) {
                const int ky = tap / 3;
                const int pb = pwarp + ky * 130 + (tap - ky * 3);
                const uint32_t sbt = sb_base + (uint32_t)(tap * 64 * ROWB);
                #pragma unroll
                for (int ks2 = 0; ks2 < 2; ks2++) {
                    const uint32_t kbyte = (uint32_t)((half * 2 + ks2) * 32);

                    // ---- hoisted fragment loads: 4 A + 4 B back-to-back ----
                    uint32_t a[4][4], bf[4][4];
                    #pragma unroll
                    for (int mt = 0; mt < 4; mt++) {
                        const uint32_t ad = sa_base
                            + (uint32_t)((pb + mt * 16) * ROWB) + kbyte + laneA;
                        LDSM_X4(a[mt][0], a[mt][1], a[mt][2], a[mt][3], ad);
                    }
                    #pragma unroll
                    for (int q = 0; q < 4; q++) {
                        const uint32_t bd = sbt
                            + (uint32_t)((16 * q + laneBc) * ROWB) + kbyte + laneBk;
                        LDSM_X4(bf[q][0], bf[q][1], bf[q][2], bf[q][3], bd);
                    }

                    // ---- 32 MMAs, no interleaved loads ----
                    #pragma unroll
                    for (int q = 0; q < 4; q++) {
                        #pragma unroll
                        for (int mt = 0; mt < 4; mt++) {
                            asm volatile(
                                "mma.sync.aligned.m16n8k16.row.col.f32.f16.f16.f32 "
                                "{%0,%1,%2,%3}, {%4,%5,%6,%7}, {%8,%9}, {%0,%1,%2,%3};"
                                : "+f"(acc[mt][2 * q][0]), "+f"(acc[mt][2 * q][1]),
                                  "+f"(acc[mt][2 * q][2]), "+f"(acc[mt][2 * q][3])
                                : "r"(a[mt][0]), "r"(a[mt][1]), "r"(a[mt][2]),
                                  "r"(a[mt][3]), "r"(bf[q][0]), "r"(bf[q][1]));
                        }
                        #pragma unroll
                        for (int mt = 0; mt < 4; mt++) {
                            asm volatile(
                                "mma.sync.aligned.m16n8k16.row.col.f32.f16.f16.f32 "
                                "{%0,%1,%2,%3}, {%4,%5,%6,%7}, {%8,%9}, {%0,%1,%2,%3};"
                                : "+f"(acc[mt][2 * q + 1][0]), "+f"(acc[mt][2 * q + 1][1]),
                                  "+f"(acc[mt][2 * q + 1][2]), "+f"(acc[mt][2 * q + 1][3])
                                : "r"(a[mt][0]), "r"(a[mt][1]), "r"(a[mt][2]),
                                  "r"(a[mt][3]), "r"(bf[q][2]), "r"(bf[q][3]));
                        }
                    }
                }
            }
        }

        // ---- prefetch next tile's slab ----
        __syncthreads();
        const int tn = t + GRID_P;
        if (tn < NTILES) {
            const int bn = tn >> 5, y0n = (tn & 31) * 4;
            stageB(bn);
            stageA4(bn, y0n, 0);
            stageA4(bn, y0n, 4);
            asm volatile("cp.async.commit_group;" ::: "memory");
        }

        // ---- epilogue (R12 verbatim) ----
        {
            const int row   = y0 + (wa >> 1);
            const int cbase = (wa & 1) * 64;
            #pragma unroll
            for (int mt = 0; mt < 4; mt++) {
                const int col = cbase + mt * 16 + g;
                #pragma unroll
                for (int nt = 0; nt < 8; nt++) {
                    const int n = nt * 8 + 2 * ti;
                    float* op = out + (((size_t)(b * C_ + n) * HW_) + row) * HW_;
                    op[col]                 = acc[mt][nt][0];
                    op[HW_ * HW_ + col]     = acc[mt][nt][1];   // cout n+1
                    op[col + 8]             = acc[mt][nt][2];
                    op[HW_ * HW_ + col + 8] = acc[mt][nt][3];
                }
            }
        }

        t = tn;
        first = false;
    }
}

extern "C" void kernel_launch(void* const* d_in, const int* in_sizes, int n_in,
                              void* d_out, int out_size) {
    (void)in_sizes; (void)n_in; (void)out_size;
    const float* x   = (const float*)d_in[0];
    const float* cov = (const float*)d_in[1];
    const float* W0  = (const float*)d_in[2];
    const float* W1  = (const float*)d_in[3];
    float* out = (float*)d_out;

    prologue_kernel<<<dim3(HW_ + 9, B_), NT>>>(x, W0, W1, cov);

    cudaFuncSetAttribute(hybrid_conv_mma_kernel,
                         cudaFuncAttributeMaxDynamicSharedMemorySize, SMEM_BYTES);
    hybrid_conv_mma_kernel<<<dim3(GRID_P), NT, SMEM_BYTES>>>(out);
}